// round 7
// baseline (speedup 1.0000x reference)
#include <cuda_runtime.h>
#include <cuda_fp16.h>
#include <cstdint>

// HawkesKT via warp-level HMMA, 2 CTAs/SM version.
// CTA tile = 128 j x 64 i; warp grid 4(M=j) x 2(N=i), warp tile 32x32.
// Dual GEMM (alpha,beta) in registers; fused decay epilogue + masked reduce over i.
// B=64, L=1024, E=128.

#define NB   64
#define SEQL 1024
#define EMB  128
#define NSK  1000

#define PITCH 272   // bytes per tile row (136 f16) -> conflict-free ldmatrix

// smem offsets (bytes)
#define SJA 0
#define SJB 34816                  // 128 x 272
#define SIA 69632                  // 64 x 272
#define SIB (69632 + 17408)
#define TSF (69632 + 34816)        // 1024 float times
#define RED (TSF + 4096)           // 2 x 128 float
#define SMEM_BYTES (RED + 1024)    // 109,568

__device__ __forceinline__ uint32_t smem_u32(const void* p) {
    uint32_t a;
    asm("{ .reg .u64 t; cvta.to.shared.u64 t, %1; cvt.u32.u64 %0, t; }" : "=r"(a) : "l"(p));
    return a;
}
__device__ __forceinline__ uint32_t pkh(float lo, float hi) {
    uint32_t r;
    asm("cvt.rn.f16x2.f32 %0, %1, %2;" : "=r"(r) : "f"(hi), "f"(lo)); // first src -> upper
    return r;
}
__device__ __forceinline__ void ldm_x4(uint32_t* r, uint32_t a) {
    asm volatile("ldmatrix.sync.aligned.m8n8.x4.shared.b16 {%0,%1,%2,%3}, [%4];"
                 : "=r"(r[0]), "=r"(r[1]), "=r"(r[2]), "=r"(r[3]) : "r"(a));
}
__device__ __forceinline__ void mma16816(float* c, const uint32_t* a, const uint32_t* b) {
    asm volatile(
        "mma.sync.aligned.m16n8k16.row.col.f32.f16.f16.f32 "
        "{%0,%1,%2,%3}, {%4,%5,%6,%7}, {%8,%9}, {%0,%1,%2,%3};"
        : "+f"(c[0]), "+f"(c[1]), "+f"(c[2]), "+f"(c[3])
        : "r"(a[0]), "r"(a[1]), "r"(a[2]), "r"(a[3]), "r"(b[0]), "r"(b[1]));
}
__device__ __forceinline__ float lg2f(float x) {
    float r; asm("lg2.approx.f32 %0, %1;" : "=f"(r) : "f"(x)); return r;
}
__device__ __forceinline__ float ex2f(float x) {
    float r; asm("ex2.approx.f32 %0, %1;" : "=f"(r) : "f"(x)); return r;
}

// Gather one table row (128 fp32) -> f16 row-major tile (PITCH-byte rows).
// r = row, h = k-half 0/1.
__device__ __forceinline__ void gather_half(const float* __restrict__ src,
                                            char* __restrict__ dstTile, int r, int h) {
    const float4* s4 = (const float4*)src + h * 16;
    char* dst = dstTile + r * PITCH + h * 128;
#pragma unroll
    for (int q = 0; q < 8; ++q) {
        float4 v0 = s4[q * 2];
        float4 v1 = s4[q * 2 + 1];
        uint4 w;
        w.x = pkh(v0.x, v0.y);
        w.y = pkh(v0.z, v0.w);
        w.z = pkh(v1.x, v1.y);
        w.w = pkh(v1.z, v1.w);
        *(uint4*)(dst + q * 16) = w;
    }
}

__global__ void __launch_bounds__(256, 2)
hawkes_hmma2(const int*   __restrict__ input,
             const float* __restrict__ problem_base,
             const float* __restrict__ skill_base,
             const float* __restrict__ alpha_inter,
             const float* __restrict__ alpha_skill,
             const float* __restrict__ beta_inter,
             const float* __restrict__ beta_skill,
             float*       __restrict__ out)
{
    extern __shared__ char smem[];
    float* tsf = (float*)(smem + TSF);
    float* red = (float*)(smem + RED);
    const uint32_t sbase = smem_u32(smem);

    const int tid  = threadIdx.x;
    const int wid  = tid >> 5;
    const int lane = tid & 31;
    const int jt   = (int)gridDim.x - 1 - (int)blockIdx.x;   // heavy tiles first
    const int b    = blockIdx.y;
    const int* __restrict__ inp = input + b * 4 * SEQL;

    const int Mw = (wid & 3) * 32;    // warp j-base within 128-row tile
    const int Nw = (wid >> 2) * 32;   // warp i-base within 64-row sI tile
    const int g  = lane >> 2;
    const int t  = lane & 3;

    // ---- times (as float) ----
    for (int i = tid; i < SEQL; i += 256) tsf[i] = (float)inp[3 * SEQL + i];

    // ---- j-side gather (alpha_skill / beta_skill) once: 512 row-half units ----
    {
        const int r = tid >> 1, h = tid & 1;
        const int sk = inp[jt * 128 + r];
        gather_half(alpha_skill + (size_t)sk * EMB, smem + SJA, r, h);
        gather_half(beta_skill  + (size_t)sk * EMB, smem + SJB, r, h);
    }
    __syncthreads();

    // ldmatrix per-thread base addresses
    const uint32_t aRow = sbase + ((uint32_t)(Mw + (lane & 15)) * PITCH) + ((lane >> 4) & 1) * 16;
    const uint32_t bRow = sbase + ((uint32_t)(Nw + (lane & 7) + ((lane >> 4) & 1) * 8) * PITCH)
                                + ((lane >> 3) & 1) * 16;

    // accumulators: ca/cb[mt][nt][4]  (mt: 2 x 16 j-rows, nt: 4 x 8 i-cols)
    float ca[2][4][4], cb[2][4][4];
    float csum[4] = {0.f, 0.f, 0.f, 0.f};

    const int jtb = jt * 128;
    float tjf[4];
    int   jr[4];
#pragma unroll
    for (int q = 0; q < 4; ++q) {
        jr[q]  = Mw + (q >> 1) * 16 + (q & 1) * 8 + g;
        tjf[q] = tsf[jtb + jr[q]];
    }

    const float C1 = 0.6213349345596119f;  // 1/ln(5)
    const int nIt = 2 * jt + 2;

    for (int it2 = 0; it2 < nIt; ++it2) {
        const int ib = it2 * 64;
        // ---- i-side gather: 256 units = 64 rows x 2 halves x 2 tables ----
        {
            const int r = tid & 63, h = (tid >> 6) & 1, tab = tid >> 7;
            const int ig = ib + r;
            const int sk  = inp[ig];
            const int lab = inp[2 * SEQL + ig];
            const int inter = sk + ((lab < 2) ? lab : 0) * NSK;
            if (tab == 0)
                gather_half(alpha_inter + (size_t)inter * EMB, smem + SIA, r, h);
            else
                gather_half(beta_inter  + (size_t)inter * EMB, smem + SIB, r, h);
        }
        __syncthreads();

        // ---- zero accum + mainloop ----
#pragma unroll
        for (int mt = 0; mt < 2; ++mt)
#pragma unroll
            for (int nt = 0; nt < 4; ++nt)
#pragma unroll
                for (int e = 0; e < 4; ++e) { ca[mt][nt][e] = 0.f; cb[mt][nt][e] = 0.f; }

#pragma unroll
        for (int ks = 0; ks < 8; ++ks) {
            uint32_t Aa[2][4], Ab[2][4];
#pragma unroll
            for (int mt = 0; mt < 2; ++mt) {
                uint32_t ao = aRow + (uint32_t)mt * 16 * PITCH + (uint32_t)ks * 32;
                ldm_x4(Aa[mt], SJA + ao);
                ldm_x4(Ab[mt], SJB + ao);
            }
#pragma unroll
            for (int np = 0; np < 2; ++np) {
                uint32_t Ba[4], Bb[4];
                uint32_t bo = bRow + (uint32_t)np * 16 * PITCH + (uint32_t)ks * 32;
                ldm_x4(Ba, SIA + bo);    // [n][k] row-major == B col-major for mma
                ldm_x4(Bb, SIB + bo);
#pragma unroll
                for (int mt = 0; mt < 2; ++mt) {
                    mma16816(ca[mt][np * 2 + 0], Aa[mt], Ba + 0);
                    mma16816(ca[mt][np * 2 + 1], Aa[mt], Ba + 2);
                    mma16816(cb[mt][np * 2 + 0], Ab[mt], Bb + 0);
                    mma16816(cb[mt][np * 2 + 1], Ab[mt], Bb + 2);
                }
            }
        }

        // ---- epilogue: decay + masked reduce over i ----
        float tif[8];
#pragma unroll
        for (int nt = 0; nt < 4; ++nt) {
            tif[nt * 2 + 0] = tsf[ib + Nw + nt * 8 + 2 * t + 0];
            tif[nt * 2 + 1] = tsf[ib + Nw + nt * 8 + 2 * t + 1];
        }
        const int  di       = ib - jtb;          // >= 0 only for last two half-tiles
        const bool needmask = (di >= 0);
#pragma unroll
        for (int mt = 0; mt < 2; ++mt)
#pragma unroll
            for (int nt = 0; nt < 4; ++nt)
#pragma unroll
                for (int e = 0; e < 4; ++e) {
                    const int q  = mt * 2 + (e >> 1);
                    const int ic = nt * 2 + (e & 1);
                    float d   = tif[ic] - tjf[q];
                    float l2  = lg2f(fabsf(d) + 1e-10f);
                    float bcs = fminf(fmaxf(cb[mt][nt][e] * C1 + C1, 0.0f), 10.0f * C1);
                    float dec = ex2f(-bcs * l2);
                    float contrib = ca[mt][nt][e] * dec;
                    if (needmask) {
                        const int il = Nw + nt * 8 + 2 * t + (e & 1);
                        if (di + il < jr[q]) csum[q] += contrib;
                    } else {
                        csum[q] += contrib;
                    }
                }
        __syncthreads();   // all warps done with sI before next gather overwrites
    }

    // ---- reduce csum across quad lanes, then across the 2 N-warps via smem ----
#pragma unroll
    for (int q = 0; q < 4; ++q) {
        csum[q] += __shfl_xor_sync(0xFFFFFFFFu, csum[q], 1);
        csum[q] += __shfl_xor_sync(0xFFFFFFFFu, csum[q], 2);
    }
    const int wn = wid >> 2;
    if (t == 0) {
#pragma unroll
        for (int q = 0; q < 4; ++q)
            red[wn * 128 + jr[q]] = csum[q];
    }
    __syncthreads();

    if (tid < 128) {
        const int j = jtb + tid;
        float s = red[tid] + red[128 + tid];
        const int sk = inp[j];
        const int pr = inp[SEQL + j];
        float x = problem_base[pr] + skill_base[sk] + s;
        out[b * SEQL + j] = 1.0f / (1.0f + ex2f(-1.4426950408889634f * x));
    }
}

extern "C" void kernel_launch(void* const* d_in, const int* in_sizes, int n_in,
                              void* d_out, int out_size) {
    const int*   input        = (const int*)  d_in[0];
    const float* problem_base = (const float*)d_in[1];
    const float* skill_base   = (const float*)d_in[2];
    const float* alpha_inter  = (const float*)d_in[3];
    const float* alpha_skill  = (const float*)d_in[4];
    const float* beta_inter   = (const float*)d_in[5];
    const float* beta_skill   = (const float*)d_in[6];
    float* outp = (float*)d_out;

    cudaFuncSetAttribute(hawkes_hmma2,
                         cudaFuncAttributeMaxDynamicSharedMemorySize, SMEM_BYTES);

    dim3 grid(SEQL / 128, NB);
    hawkes_hmma2<<<grid, 256, SMEM_BYTES>>>(input, problem_base, skill_base,
                                            alpha_inter, alpha_skill,
                                            beta_inter, beta_skill, outp);
}

// round 8
// speedup vs baseline: 1.1183x; 1.1183x over previous
#include <cuda_runtime.h>
#include <cuda_fp16.h>
#include <cstdint>

// HawkesKT via warp-level HMMA, double-buffered i-tiles.
// CTA = (j-tile 128, batch); warp grid 4(Mj) x 2(Ni), warp tile 32x64.
// Per iter: gather(it+1) -> buf^1 overlaps mainloop(it) on buf; ONE sync/iter.
// B=64, L=1024, E=128.

#define NB   64
#define SEQL 1024
#define EMB  128
#define NSK  1000

#define PITCH 272   // bytes per tile row (136 f16) -> conflict-free ldmatrix

// smem offsets (bytes)
#define SJA 0
#define SJB 34816                    // 128 x 272 each
#define SIBUF 69632                  // two (SIA+SIB) buffers of 69632 each
#define SIBUF_SZ 69632
#define TSF (69632 + 2 * 69632)      // 208896: 1024 float times
#define RED (TSF + 4096)             // 212992: 2 x 128 float
#define SMEM_BYTES (RED + 1024)      // 214016

__device__ __forceinline__ uint32_t smem_u32(const void* p) {
    uint32_t a;
    asm("{ .reg .u64 t; cvta.to.shared.u64 t, %1; cvt.u32.u64 %0, t; }" : "=r"(a) : "l"(p));
    return a;
}
__device__ __forceinline__ uint32_t pkh(float lo, float hi) {
    uint32_t r;
    asm("cvt.rn.f16x2.f32 %0, %1, %2;" : "=r"(r) : "f"(hi), "f"(lo)); // first src -> upper
    return r;
}
__device__ __forceinline__ void ldm_x4(uint32_t* r, uint32_t a) {
    asm volatile("ldmatrix.sync.aligned.m8n8.x4.shared.b16 {%0,%1,%2,%3}, [%4];"
                 : "=r"(r[0]), "=r"(r[1]), "=r"(r[2]), "=r"(r[3]) : "r"(a));
}
__device__ __forceinline__ void mma16816(float* c, const uint32_t* a, const uint32_t* b) {
    asm volatile(
        "mma.sync.aligned.m16n8k16.row.col.f32.f16.f16.f32 "
        "{%0,%1,%2,%3}, {%4,%5,%6,%7}, {%8,%9}, {%0,%1,%2,%3};"
        : "+f"(c[0]), "+f"(c[1]), "+f"(c[2]), "+f"(c[3])
        : "r"(a[0]), "r"(a[1]), "r"(a[2]), "r"(a[3]), "r"(b[0]), "r"(b[1]));
}
__device__ __forceinline__ float lg2f(float x) {
    float r; asm("lg2.approx.f32 %0, %1;" : "=f"(r) : "f"(x)); return r;
}
__device__ __forceinline__ float ex2f(float x) {
    float r; asm("ex2.approx.f32 %0, %1;" : "=f"(r) : "f"(x)); return r;
}

// Gather one table row (128 fp32) -> f16 row-major tile (PITCH-byte rows).
__device__ __forceinline__ void gather_half(const float* __restrict__ src,
                                            char* __restrict__ dstTile, int r, int h) {
    const float4* s4 = (const float4*)src + h * 16;
    char* dst = dstTile + r * PITCH + h * 128;
#pragma unroll
    for (int q = 0; q < 8; ++q) {
        float4 v0 = s4[q * 2];
        float4 v1 = s4[q * 2 + 1];
        uint4 w;
        w.x = pkh(v0.x, v0.y);
        w.y = pkh(v0.z, v0.w);
        w.z = pkh(v1.x, v1.y);
        w.w = pkh(v1.z, v1.w);
        *(uint4*)(dst + q * 16) = w;
    }
}

__global__ void __launch_bounds__(256, 1)
hawkes_hmma_db(const int*   __restrict__ input,
               const float* __restrict__ problem_base,
               const float* __restrict__ skill_base,
               const float* __restrict__ alpha_inter,
               const float* __restrict__ alpha_skill,
               const float* __restrict__ beta_inter,
               const float* __restrict__ beta_skill,
               float*       __restrict__ out)
{
    extern __shared__ char smem[];
    float* tsf = (float*)(smem + TSF);
    float* red = (float*)(smem + RED);
    const uint32_t sbase = smem_u32(smem);

    const int tid  = threadIdx.x;
    const int wid  = tid >> 5;
    const int lane = tid & 31;
    const int jt   = (int)gridDim.x - 1 - (int)blockIdx.x;   // heavy tiles first
    const int b    = blockIdx.y;
    const int* __restrict__ inp = input + b * 4 * SEQL;

    const int Mw = (wid & 3) * 32;    // warp j-base within tile
    const int Nw = (wid >> 2) * 64;   // warp i-base within tile
    const int g  = lane >> 2;
    const int t  = lane & 3;

    // gather role for this thread (row r, k-half h)
    const int gr = tid >> 1, gh = tid & 1;

    // ---- times (as float) ----
    for (int i = tid; i < SEQL; i += 256) tsf[i] = (float)inp[3 * SEQL + i];

    // ---- j-side gather once ----
    {
        const int sk = inp[jt * 128 + gr];
        gather_half(alpha_skill + (size_t)sk * EMB, smem + SJA, gr, gh);
        gather_half(beta_skill  + (size_t)sk * EMB, smem + SJB, gr, gh);
    }

    // ---- prologue: i-tile 0 into buf 0 ----
    {
        const int sk  = inp[gr];
        const int lab = inp[2 * SEQL + gr];
        const int inter = sk + ((lab < 2) ? lab : 0) * NSK;
        gather_half(alpha_inter + (size_t)inter * EMB, smem + SIBUF, gr, gh);
        gather_half(beta_inter  + (size_t)inter * EMB, smem + SIBUF + 34816, gr, gh);
    }
    __syncthreads();

    // ldmatrix per-thread base addresses (row parts; tile base added at use)
    const uint32_t aRow = sbase + ((uint32_t)(Mw + (lane & 15)) * PITCH) + ((lane >> 4) & 1) * 16;
    const uint32_t bRowRel = ((uint32_t)(Nw + (lane & 7) + ((lane >> 4) & 1) * 8) * PITCH)
                             + ((lane >> 3) & 1) * 16;

    float ca[2][8][4], cb[2][8][4];
    float csum[4] = {0.f, 0.f, 0.f, 0.f};

    const int jtb = jt * 128;
    float tjf[4];
    int   jr[4];
#pragma unroll
    for (int q = 0; q < 4; ++q) {
        jr[q]  = Mw + (q >> 1) * 16 + (q & 1) * 8 + g;
        tjf[q] = tsf[jtb + jr[q]];
    }

    const float C1 = 0.6213349345596119f;  // 1/ln(5)

    for (int it = 0; it <= jt; ++it) {
        const uint32_t bufc = SIBUF + (uint32_t)(it & 1) * SIBUF_SZ;

        // ---- overlapped gather of tile it+1 into the other buffer ----
        if (it < jt) {
            const uint32_t bufn = SIBUF + (uint32_t)((it + 1) & 1) * SIBUF_SZ;
            const int ig = (it + 1) * 128 + gr;
            const int sk  = inp[ig];
            const int lab = inp[2 * SEQL + ig];
            const int inter = sk + ((lab < 2) ? lab : 0) * NSK;
            gather_half(alpha_inter + (size_t)inter * EMB, smem + bufn, gr, gh);
            gather_half(beta_inter  + (size_t)inter * EMB, smem + bufn + 34816, gr, gh);
        }

        // ---- zero accum + mainloop on buf[it&1] ----
#pragma unroll
        for (int mt = 0; mt < 2; ++mt)
#pragma unroll
            for (int nt = 0; nt < 8; ++nt)
#pragma unroll
                for (int e = 0; e < 4; ++e) { ca[mt][nt][e] = 0.f; cb[mt][nt][e] = 0.f; }

        const uint32_t bRowA = sbase + bufc + bRowRel;           // SIA of cur buf
        const uint32_t bRowB = sbase + bufc + 34816 + bRowRel;   // SIB of cur buf

#pragma unroll
        for (int ks = 0; ks < 8; ++ks) {
            uint32_t Aa[2][4], Ab[2][4];
#pragma unroll
            for (int mt = 0; mt < 2; ++mt) {
                uint32_t ao = aRow + (uint32_t)mt * 16 * PITCH + (uint32_t)ks * 32;
                ldm_x4(Aa[mt], SJA + ao);
                ldm_x4(Ab[mt], SJB + ao);
            }
#pragma unroll
            for (int np = 0; np < 4; ++np) {
                uint32_t Ba[4], Bb[4];
                uint32_t bo = (uint32_t)np * 16 * PITCH + (uint32_t)ks * 32;
                ldm_x4(Ba, bRowA + bo);   // [n][k] row-major == B col-major for mma
                ldm_x4(Bb, bRowB + bo);
#pragma unroll
                for (int mt = 0; mt < 2; ++mt) {
                    mma16816(ca[mt][np * 2 + 0], Aa[mt], Ba + 0);
                    mma16816(ca[mt][np * 2 + 1], Aa[mt], Ba + 2);
                    mma16816(cb[mt][np * 2 + 0], Ab[mt], Bb + 0);
                    mma16816(cb[mt][np * 2 + 1], Ab[mt], Bb + 2);
                }
            }
        }

        // ---- epilogue: decay + masked reduce over i ----
        const int itb = it * 128;
        float tif[16];
#pragma unroll
        for (int nt = 0; nt < 8; ++nt) {
            tif[nt * 2 + 0] = tsf[itb + Nw + nt * 8 + 2 * t + 0];
            tif[nt * 2 + 1] = tsf[itb + Nw + nt * 8 + 2 * t + 1];
        }
        const bool diag = (it == jt);
#pragma unroll
        for (int mt = 0; mt < 2; ++mt)
#pragma unroll
            for (int nt = 0; nt < 8; ++nt)
#pragma unroll
                for (int e = 0; e < 4; ++e) {
                    const int q  = mt * 2 + (e >> 1);
                    const int ic = nt * 2 + (e & 1);
                    float d   = tif[ic] - tjf[q];
                    float l2  = lg2f(fabsf(d) + 1e-10f);
                    float bcs = fminf(fmaxf(cb[mt][nt][e] * C1 + C1, 0.0f), 10.0f * C1);
                    float dec = ex2f(-bcs * l2);
                    float contrib = ca[mt][nt][e] * dec;
                    if (diag) {
                        if ((Nw + nt * 8 + 2 * t + (e & 1)) < jr[q]) csum[q] += contrib;
                    } else {
                        csum[q] += contrib;
                    }
                }

        // one sync per iter: publishes next buf's stores, retires cur buf reads
        __syncthreads();
    }

    // ---- reduce csum across quad lanes, then across the 2 N-warps via smem ----
#pragma unroll
    for (int q = 0; q < 4; ++q) {
        csum[q] += __shfl_xor_sync(0xFFFFFFFFu, csum[q], 1);
        csum[q] += __shfl_xor_sync(0xFFFFFFFFu, csum[q], 2);
    }
    const int wn = wid >> 2;
    if (t == 0) {
#pragma unroll
        for (int q = 0; q < 4; ++q)
            red[wn * 128 + jr[q]] = csum[q];
    }
    __syncthreads();

    if (tid < 128) {
        const int j = jtb + tid;
        float s = red[tid] + red[128 + tid];
        const int sk = inp[j];
        const int pr = inp[SEQL + j];
        float x = problem_base[pr] + skill_base[sk] + s;
        out[b * SEQL + j] = 1.0f / (1.0f + ex2f(-1.4426950408889634f * x));
    }
}

extern "C" void kernel_launch(void* const* d_in, const int* in_sizes, int n_in,
                              void* d_out, int out_size) {
    const int*   input        = (const int*)  d_in[0];
    const float* problem_base = (const float*)d_in[1];
    const float* skill_base   = (const float*)d_in[2];
    const float* alpha_inter  = (const float*)d_in[3];
    const float* alpha_skill  = (const float*)d_in[4];
    const float* beta_inter   = (const float*)d_in[5];
    const float* beta_skill   = (const float*)d_in[6];
    float* outp = (float*)d_out;

    cudaFuncSetAttribute(hawkes_hmma_db,
                         cudaFuncAttributeMaxDynamicSharedMemorySize, SMEM_BYTES);

    dim3 grid(SEQL / 128, NB);
    hawkes_hmma_db<<<grid, 256, SMEM_BYTES>>>(input, problem_base, skill_base,
                                              alpha_inter, alpha_skill,
                                              beta_inter, beta_skill, outp);
}

// round 9
// speedup vs baseline: 1.4206x; 1.2703x over previous
#include <cuda_runtime.h>
#include <cuda_fp16.h>
#include <cstdint>

// HawkesKT via warp-level HMMA, 512-thread CTA (16 warps, 4 warps/SMSP).
// CTA = (j-tile 128, batch); warp grid 4(Mj) x 4(Ni), warp tile 32x32.
// Dual GEMM (alpha,beta) in registers; fused decay epilogue + masked reduce over i.
// B=64, L=1024, E=128.

#define NB   64
#define SEQL 1024
#define EMB  128
#define NSK  1000
#define NTHR 512

#define PITCH 272   // bytes per tile row (136 f16) -> conflict-free ldmatrix

// smem offsets (bytes)
#define SJA 0
#define SJB 34816                  // 128 x 272 each
#define SIA 69632
#define SIB 104448
#define TSF 139264                 // 1024 float times
#define RED 143360                 // 4 x 128 float
#define SMEM_BYTES (143360 + 2048) // 145408

__device__ __forceinline__ uint32_t smem_u32(const void* p) {
    uint32_t a;
    asm("{ .reg .u64 t; cvta.to.shared.u64 t, %1; cvt.u32.u64 %0, t; }" : "=r"(a) : "l"(p));
    return a;
}
__device__ __forceinline__ uint32_t pkh(float lo, float hi) {
    uint32_t r;
    asm("cvt.rn.f16x2.f32 %0, %1, %2;" : "=r"(r) : "f"(hi), "f"(lo)); // first src -> upper
    return r;
}
__device__ __forceinline__ void ldm_x4(uint32_t* r, uint32_t a) {
    asm volatile("ldmatrix.sync.aligned.m8n8.x4.shared.b16 {%0,%1,%2,%3}, [%4];"
                 : "=r"(r[0]), "=r"(r[1]), "=r"(r[2]), "=r"(r[3]) : "r"(a));
}
__device__ __forceinline__ void mma16816(float* c, const uint32_t* a, const uint32_t* b) {
    asm volatile(
        "mma.sync.aligned.m16n8k16.row.col.f32.f16.f16.f32 "
        "{%0,%1,%2,%3}, {%4,%5,%6,%7}, {%8,%9}, {%0,%1,%2,%3};"
        : "+f"(c[0]), "+f"(c[1]), "+f"(c[2]), "+f"(c[3])
        : "r"(a[0]), "r"(a[1]), "r"(a[2]), "r"(a[3]), "r"(b[0]), "r"(b[1]));
}
__device__ __forceinline__ float lg2f(float x) {
    float r; asm("lg2.approx.f32 %0, %1;" : "=f"(r) : "f"(x)); return r;
}
__device__ __forceinline__ float ex2f(float x) {
    float r; asm("ex2.approx.f32 %0, %1;" : "=f"(r) : "f"(x)); return r;
}

// Gather one table row-half (64 fp32 -> 64 f16) into tile (PITCH-byte rows).
__device__ __forceinline__ void gather_half(const float* __restrict__ src,
                                            char* __restrict__ dstTile, int r, int h) {
    const float4* s4 = (const float4*)src + h * 16;
    char* dst = dstTile + r * PITCH + h * 128;
#pragma unroll
    for (int q = 0; q < 8; ++q) {
        float4 v0 = s4[q * 2];
        float4 v1 = s4[q * 2 + 1];
        uint4 w;
        w.x = pkh(v0.x, v0.y);
        w.y = pkh(v0.z, v0.w);
        w.z = pkh(v1.x, v1.y);
        w.w = pkh(v1.z, v1.w);
        *(uint4*)(dst + q * 16) = w;
    }
}

__global__ void __launch_bounds__(NTHR, 1)
hawkes_hmma16(const int*   __restrict__ input,
              const float* __restrict__ problem_base,
              const float* __restrict__ skill_base,
              const float* __restrict__ alpha_inter,
              const float* __restrict__ alpha_skill,
              const float* __restrict__ beta_inter,
              const float* __restrict__ beta_skill,
              float*       __restrict__ out)
{
    extern __shared__ char smem[];
    float* tsf = (float*)(smem + TSF);
    float* red = (float*)(smem + RED);
    const uint32_t sbase = smem_u32(smem);

    const int tid  = threadIdx.x;
    const int wid  = tid >> 5;
    const int lane = tid & 31;
    const int jt   = (int)gridDim.x - 1 - (int)blockIdx.x;   // heavy tiles first
    const int b    = blockIdx.y;
    const int* __restrict__ inp = input + b * 4 * SEQL;

    const int Mw = (wid & 3) * 32;    // warp j-base
    const int Nw = (wid >> 2) * 32;   // warp i-base
    const int g  = lane >> 2;
    const int t  = lane & 3;

    // gather role: 512 units = 128 rows x 2 halves x 2 tables
    const int gr = tid >> 2, gh = (tid >> 1) & 1, gtab = tid & 1;

    // ---- times (as float) ----
    for (int i = tid; i < SEQL; i += NTHR) tsf[i] = (float)inp[3 * SEQL + i];

    // ---- j-side gather once ----
    {
        const int sk = inp[jt * 128 + gr];
        if (gtab == 0) gather_half(alpha_skill + (size_t)sk * EMB, smem + SJA, gr, gh);
        else           gather_half(beta_skill  + (size_t)sk * EMB, smem + SJB, gr, gh);
    }
    __syncthreads();

    // ldmatrix per-thread base addresses
    const uint32_t aRow = sbase + ((uint32_t)(Mw + (lane & 15)) * PITCH) + ((lane >> 4) & 1) * 16;
    const uint32_t bRow = sbase + ((uint32_t)(Nw + (lane & 7) + ((lane >> 4) & 1) * 8) * PITCH)
                                + ((lane >> 3) & 1) * 16;

    // accumulators: ca/cb[mt][nt][4]  (mt: 2 x 16 j-rows, nt: 4 x 8 i-cols)
    float ca[2][4][4], cb[2][4][4];
    float csum[4] = {0.f, 0.f, 0.f, 0.f};

    const int jtb = jt * 128;
    float tjf[4];
    int   jr[4];
#pragma unroll
    for (int q = 0; q < 4; ++q) {
        jr[q]  = Mw + (q >> 1) * 16 + (q & 1) * 8 + g;
        tjf[q] = tsf[jtb + jr[q]];
    }

    const float C1 = 0.6213349345596119f;  // 1/ln(5)

    for (int it = 0; it <= jt; ++it) {
        // ---- i-side gather ----
        {
            const int ig = it * 128 + gr;
            const int sk  = inp[ig];
            const int lab = inp[2 * SEQL + ig];
            const int inter = sk + ((lab < 2) ? lab : 0) * NSK;
            if (gtab == 0) gather_half(alpha_inter + (size_t)inter * EMB, smem + SIA, gr, gh);
            else           gather_half(beta_inter  + (size_t)inter * EMB, smem + SIB, gr, gh);
        }
        __syncthreads();

        // ---- zero accum + mainloop ----
#pragma unroll
        for (int mt = 0; mt < 2; ++mt)
#pragma unroll
            for (int nt = 0; nt < 4; ++nt)
#pragma unroll
                for (int e = 0; e < 4; ++e) { ca[mt][nt][e] = 0.f; cb[mt][nt][e] = 0.f; }

#pragma unroll
        for (int ks = 0; ks < 8; ++ks) {
            uint32_t Aa[2][4], Ab[2][4];
#pragma unroll
            for (int mt = 0; mt < 2; ++mt) {
                uint32_t ao = aRow + (uint32_t)mt * 16 * PITCH + (uint32_t)ks * 32;
                ldm_x4(Aa[mt], SJA + ao);
                ldm_x4(Ab[mt], SJB + ao);
            }
#pragma unroll
            for (int np = 0; np < 2; ++np) {
                uint32_t Ba[4], Bb[4];
                uint32_t bo = bRow + (uint32_t)np * 16 * PITCH + (uint32_t)ks * 32;
                ldm_x4(Ba, SIA + bo);   // [n][k] row-major == B col-major for mma
                ldm_x4(Bb, SIB + bo);
#pragma unroll
                for (int mt = 0; mt < 2; ++mt) {
                    mma16816(ca[mt][np * 2 + 0], Aa[mt], Ba + 0);
                    mma16816(ca[mt][np * 2 + 1], Aa[mt], Ba + 2);
                    mma16816(cb[mt][np * 2 + 0], Ab[mt], Bb + 0);
                    mma16816(cb[mt][np * 2 + 1], Ab[mt], Bb + 2);
                }
            }
        }

        // ---- epilogue: decay + masked reduce over i ----
        const int itb = it * 128;
        float tif[8];
#pragma unroll
        for (int nt = 0; nt < 4; ++nt) {
            tif[nt * 2 + 0] = tsf[itb + Nw + nt * 8 + 2 * t + 0];
            tif[nt * 2 + 1] = tsf[itb + Nw + nt * 8 + 2 * t + 1];
        }
        const bool diag = (it == jt);
#pragma unroll
        for (int mt = 0; mt < 2; ++mt)
#pragma unroll
            for (int nt = 0; nt < 4; ++nt)
#pragma unroll
                for (int e = 0; e < 4; ++e) {
                    const int q  = mt * 2 + (e >> 1);
                    const int ic = nt * 2 + (e & 1);
                    float d   = tif[ic] - tjf[q];
                    float l2  = lg2f(fabsf(d) + 1e-10f);
                    float bcs = fminf(fmaxf(cb[mt][nt][e] * C1 + C1, 0.0f), 10.0f * C1);
                    float dec = ex2f(-bcs * l2);
                    float contrib = ca[mt][nt][e] * dec;
                    if (diag) {
                        if ((Nw + nt * 8 + 2 * t + (e & 1)) < jr[q]) csum[q] += contrib;
                    } else {
                        csum[q] += contrib;
                    }
                }
        __syncthreads();   // all warps done with sI before next gather overwrites
    }

    // ---- reduce csum across quad lanes, then across the 4 N-warps via smem ----
#pragma unroll
    for (int q = 0; q < 4; ++q) {
        csum[q] += __shfl_xor_sync(0xFFFFFFFFu, csum[q], 1);
        csum[q] += __shfl_xor_sync(0xFFFFFFFFu, csum[q], 2);
    }
    const int wn = wid >> 2;
    if (t == 0) {
#pragma unroll
        for (int q = 0; q < 4; ++q)
            red[wn * 128 + jr[q]] = csum[q];
    }
    __syncthreads();

    if (tid < 128) {
        const int j = jtb + tid;
        float s = (red[tid] + red[128 + tid]) + (red[256 + tid] + red[384 + tid]);
        const int sk = inp[j];
        const int pr = inp[SEQL + j];
        float x = problem_base[pr] + skill_base[sk] + s;
        out[b * SEQL + j] = 1.0f / (1.0f + ex2f(-1.4426950408889634f * x));
    }
}

extern "C" void kernel_launch(void* const* d_in, const int* in_sizes, int n_in,
                              void* d_out, int out_size) {
    const int*   input        = (const int*)  d_in[0];
    const float* problem_base = (const float*)d_in[1];
    const float* skill_base   = (const float*)d_in[2];
    const float* alpha_inter  = (const float*)d_in[3];
    const float* alpha_skill  = (const float*)d_in[4];
    const float* beta_inter   = (const float*)d_in[5];
    const float* beta_skill   = (const float*)d_in[6];
    float* outp = (float*)d_out;

    cudaFuncSetAttribute(hawkes_hmma16,
                         cudaFuncAttributeMaxDynamicSharedMemorySize, SMEM_BYTES);

    dim3 grid(SEQL / 128, NB);
    hawkes_hmma16<<<grid, NTHR, SMEM_BYTES>>>(input, problem_base, skill_base,
                                              alpha_inter, alpha_skill,
                                              beta_inter, beta_skill, outp);
}